// round 10
// baseline (speedup 1.0000x reference)
#include <cuda_runtime.h>
#include <cuda_bf16.h>
#include <cstdint>
#include <cstddef>

// TMPNN: 7 steps of x += poly(x) @ W, M=131072, N=32, symmetric-folded basis.
// R10: A-fragments built directly in registers (no P SMEM, no STS, no ldmatrix).
// Per-lane column selection done by DATA rotation (lane c loads x-pairs rotated
// by 4c chunks), so one lane-uniform compile-time recipe per fragment slot keeps
// the warp convergent for mma.sync. Shift-orbit covering design over K=624
// (39 k-tiles); duplicate monomials get W=0 in the B table. B tables in global
// (L1/L2-shared across CTAs). Residual in MMA accumulators. 4 CTAs/SM.
//
// Template slots s (2 per k-tile, 78 total; lane c applies pair-shift +4c):
//   s<72:  d = s>>3 (0=diag), a = (s>>1)&3, h = s&1
//          cell: u = half h of pair (a+4c), v = pair (a+d+4c)
//          monomials {2A+h, 2B}, {2A+h, 2B+1} with A=(a+4c)%16, B=(A+d)%16
//          W=0 for: diag h=1 j=0 (dup of h=0 j=1); d=8 with A>=8 (reversed copy)
//   72..75: linear pair (s-72+4c)  |  76: (bias=1, 0)  |  77: zero pad

namespace {

constexpr int N_STEPS = 7;
constexpr int NKT   = 39;            // k-tiles of 16 (K_mma = 624)
constexpr int XBSTR = 20;            // xsb row stride (uint32 bf16x2), 80 B

constexpr int OFF_XB = 0;                       // u32 xsb[128][20]
constexpr int SMEM_BYTES = 128 * XBSTR * 4;     // 10240

__device__ __forceinline__ uint32_t pack2(float lo, float hi) {
    uint32_t r;
    asm("cvt.rn.bf16x2.f32 %0, %1, %2;" : "=r"(r) : "f"(hi), "f"(lo));
    return r;
}

__device__ __forceinline__ void mma16816(float* c, uint32_t a0, uint32_t a1,
                                         uint32_t a2, uint32_t a3,
                                         uint32_t b0, uint32_t b1) {
    asm volatile("mma.sync.aligned.m16n8k16.row.col.f32.bf16.bf16.f32 "
                 "{%0,%1,%2,%3}, {%4,%5,%6,%7}, {%8,%9}, {%0,%1,%2,%3};"
                 : "+f"(c[0]), "+f"(c[1]), "+f"(c[2]), "+f"(c[3])
                 : "r"(a0), "r"(a1), "r"(a2), "r"(a3), "r"(b0), "r"(b1));
}

// ---- slot maps (compile-time) ----
__host__ __device__ constexpr int sD(int S)  { return S >> 3; }
__host__ __device__ constexpr int sA(int S)  { return (S >> 1) & 3; }
__host__ __device__ constexpr int sH(int S)  { return S & 1; }
__host__ __device__ constexpr int sI1(int S) { return sD(S) == 0 ? sA(S) : sA(S) + sD(S); }

// A-fragment pair for template slot S from rotated pair regs y[0..11].
template <int S>
__device__ __forceinline__ uint32_t pairA(const uint32_t* y) {
    if (S >= 77) return 0u;                 // zero pad
    if (S == 76) return 0x00003F80u;        // {bias=1, 0}
    if (S >= 72) return y[S - 72];          // linear: natural pair
    const uint32_t s0 = y[sA(S)];
    const uint32_t u = __byte_perm(s0, s0, sH(S) ? 0x3232 : 0x1010);  // bcast half
    uint32_t r;
    asm("mul.rn.bf16x2 %0, %1, %2;" : "=r"(r) : "r"(u), "r"(y[sI1(S)]));
    return r;
}

// ---- runtime W for B-table init (mirrors the slot map; dups get 0) ----
__device__ float wsym(const float* __restrict__ W, int i, int m, int n) {
    if (i == m) return __ldg(&W[(33 + i * 32 + i) * 32 + n]);
    return __ldg(&W[(33 + i * 32 + m) * 32 + n]) + __ldg(&W[(33 + m * 32 + i) * 32 + n]);
}

__device__ float wcell(const float* __restrict__ W, int S, int c, int j, int n) {
    if (S >= 77) return 0.0f;
    if (S == 76) return (j == 0 && c == 0) ? __ldg(&W[n]) : 0.0f;
    if (S >= 72) {
        const int pv = ((S - 72) + 4 * c) & 15;
        return __ldg(&W[(1 + 2 * pv + j) * 32 + n]);
    }
    const int d = S >> 3, a = (S >> 1) & 3, h = S & 1;
    const int A = (a + 4 * c) & 15;
    if (d == 0) {
        if (h == 1 && j == 0) return 0.0f;           // dup {2A+1, 2A}
        return wsym(W, 2 * A + h, 2 * A + j, n);
    }
    if (d == 8 && A >= 8) return 0.0f;               // reversed copy of {A-8, A}
    const int B = (A + d) & 15;
    return wsym(W, 2 * A + h, 2 * B + j, n);
}

} // namespace

// B-fragment tables: [0, NKT*32) = Lo (n 0..15), [NKT*32, 2*NKT*32) = Hi.
__device__ uint4 g_Bf[2 * NKT * 32];

__global__ void bf_init_kernel(const float* __restrict__ W) {
    const int idx = blockIdx.x * blockDim.x + threadIdx.x;
    if (idx >= 2 * NKT * 32) return;
    const int t   = idx / (NKT * 32);
    const int rem = idx - t * (NKT * 32);
    const int kt  = rem >> 5;
    const int l   = rem & 31;
    const int c   = l & 3;
    const int n0  = (l >> 2) + t * 16;
    uint4 q;
    q.x = pack2(wcell(W, 2 * kt,     c, 0, n0),     wcell(W, 2 * kt,     c, 1, n0));
    q.y = pack2(wcell(W, 2 * kt + 1, c, 0, n0),     wcell(W, 2 * kt + 1, c, 1, n0));
    q.z = pack2(wcell(W, 2 * kt,     c, 0, n0 + 8), wcell(W, 2 * kt,     c, 1, n0 + 8));
    q.w = pack2(wcell(W, 2 * kt + 1, c, 0, n0 + 8), wcell(W, 2 * kt + 1, c, 1, n0 + 8));
    g_Bf[idx] = q;
}

__global__ void __launch_bounds__(256, 4)
tmpnn_kernel(const float* __restrict__ X, float* __restrict__ out)
{
    extern __shared__ char smem[];
    uint32_t* xsb = reinterpret_cast<uint32_t*>(smem + OFF_XB); // [128][20] bf16x2

    const int tid  = threadIdx.x;
    const int lane = tid & 31;
    const int w    = tid >> 5;
    const int c    = lane & 3;               // fragment column group / data rotation
    const int r0   = w * 16 + (lane >> 2);   // this lane's mma rows: r0, r0+8
    const int cb   = c * 2;                  // accumulator col base

    // ---- stage bf16x2 X copy ----
    const float* Xb = X + (size_t)blockIdx.x * 4096;
    for (int i = tid; i < 128 * 16; i += 256) {
        const int rr = i >> 4, j = i & 15;
        const float2 v = __ldg(reinterpret_cast<const float2*>(Xb + rr * 32 + 2 * j));
        xsb[rr * XBSTR + j] = pack2(v.x, v.y);
    }

    // ---- fp32 residual in mma-accumulator layout ----
    float res[4][4];
    #pragma unroll
    for (int nt = 0; nt < 4; ++nt) {
        const int cc = nt * 8 + cb;
        const float2 v0 = __ldg(reinterpret_cast<const float2*>(Xb + r0 * 32 + cc));
        const float2 v1 = __ldg(reinterpret_cast<const float2*>(Xb + (r0 + 8) * 32 + cc));
        res[nt][0] = v0.x; res[nt][1] = v0.y;
        res[nt][2] = v1.x; res[nt][3] = v1.y;
    }
    __syncthreads();   // xsb visible (only CTA-wide barrier)

    const uint4* BfL = g_Bf + lane;
    const uint4* BfH = g_Bf + (NKT * 32) + lane;

    for (int step = 0; step < N_STEPS; ++step) {
        const bool full = (step != N_STEPS - 1);   // last step: only n 0..7 needed

        // rotated pair regs: y[i] = xpair[(i + 4c) & 15]; only y[0..11] used.
        uint32_t y0[12], y1[12];
        #pragma unroll
        for (int q = 0; q < 3; ++q) {
            const int ch = ((q + c) & 3) * 4;
            const uint4 t0 = *reinterpret_cast<const uint4*>(&xsb[r0 * XBSTR + ch]);
            const uint4 t1 = *reinterpret_cast<const uint4*>(&xsb[(r0 + 8) * XBSTR + ch]);
            y0[4*q] = t0.x; y0[4*q+1] = t0.y; y0[4*q+2] = t0.z; y0[4*q+3] = t0.w;
            y1[4*q] = t1.x; y1[4*q+1] = t1.y; y1[4*q+2] = t1.z; y1[4*q+3] = t1.w;
        }

#define TILE(T) {                                                        \
            const uint32_t a0 = pairA<2*(T)>(y0);                        \
            const uint32_t a1 = pairA<2*(T)>(y1);                        \
            const uint32_t a2 = pairA<2*(T)+1>(y0);                      \
            const uint32_t a3 = pairA<2*(T)+1>(y1);                      \
            const uint4 ql = __ldg(BfL + (T) * 32);                      \
            mma16816(res[0], a0, a1, a2, a3, ql.x, ql.y);                \
            if (full) {                                                  \
                mma16816(res[1], a0, a1, a2, a3, ql.z, ql.w);            \
                const uint4 qh = __ldg(BfH + (T) * 32);                  \
                mma16816(res[2], a0, a1, a2, a3, qh.x, qh.y);            \
                mma16816(res[3], a0, a1, a2, a3, qh.z, qh.w);            \
            }                                                            \
        }
        TILE(0)  TILE(1)  TILE(2)  TILE(3)  TILE(4)  TILE(5)  TILE(6)
        TILE(7)  TILE(8)  TILE(9)  TILE(10) TILE(11) TILE(12) TILE(13)
        TILE(14) TILE(15) TILE(16) TILE(17) TILE(18) TILE(19) TILE(20)
        TILE(21) TILE(22) TILE(23) TILE(24) TILE(25) TILE(26) TILE(27)
        TILE(28) TILE(29) TILE(30) TILE(31) TILE(32) TILE(33) TILE(34)
        TILE(35) TILE(36) TILE(37) TILE(38)
#undef TILE

        // ---- epilogue: refresh bf16x2 copy from accumulator registers ----
        if (full) {
            __syncwarp();   // y reads of this step done before xsb overwrite
            #pragma unroll
            for (int nt = 0; nt < 4; ++nt) {
                const int cc = nt * 8 + cb;
                xsb[r0 * XBSTR + (cc >> 1)]       = pack2(res[nt][0], res[nt][1]);
                xsb[(r0 + 8) * XBSTR + (cc >> 1)] = pack2(res[nt][2], res[nt][3]);
            }
            __syncwarp();   // visible to next step's y reload
        }
    }

    if (c == 0) {
        out[(size_t)blockIdx.x * 128 + r0]     = res[0][0];
        out[(size_t)blockIdx.x * 128 + r0 + 8] = res[0][2];
    }
}

extern "C" void kernel_launch(void* const* d_in, const int* in_sizes, int n_in,
                              void* d_out, int out_size) {
    const float* X = (const float*)d_in[0];
    const float* W = (const float*)d_in[1];
    float* out = (float*)d_out;
    const int rows = in_sizes[0] / 32;
    const int blocks = rows / 128;
    bf_init_kernel<<<(2 * NKT * 32 + 255) / 256, 256>>>(W);
    cudaFuncSetAttribute(tmpnn_kernel, cudaFuncAttributeMaxDynamicSharedMemorySize,
                         SMEM_BYTES);
    tmpnn_kernel<<<blocks, 256, SMEM_BYTES>>>(X, out);
}

// round 11
// speedup vs baseline: 7.7669x; 7.7669x over previous
#include <cuda_runtime.h>
#include <cuda_bf16.h>
#include <cstdint>
#include <cstddef>

// TMPNN: 7 steps of x += poly(x) @ W, M=131072, N=32, symmetric-folded basis.
// R11 = R10 at 3 CTAs/SM: A-fragments built directly in registers (no P SMEM,
// no STS, no ldmatrix); per-lane column selection via data rotation; shift-orbit
// covering design K=624 (39 k-tiles), duplicate monomials get W=0 in B.
// R10 failed only because __launch_bounds__(256,4) forced 64 regs -> local
// spills (DRAM 45%). 3 CTAs/SM gives an 85-reg budget -> no spills.

namespace {

constexpr int N_STEPS = 7;
constexpr int NKT   = 39;            // k-tiles of 16 (K_mma = 624)
constexpr int XBSTR = 20;            // xsb row stride (uint32 bf16x2), 80 B

constexpr int OFF_XB = 0;                       // u32 xsb[128][20]
constexpr int SMEM_BYTES = 128 * XBSTR * 4;     // 10240

__device__ __forceinline__ uint32_t pack2(float lo, float hi) {
    uint32_t r;
    asm("cvt.rn.bf16x2.f32 %0, %1, %2;" : "=r"(r) : "f"(hi), "f"(lo));
    return r;
}

__device__ __forceinline__ void mma16816(float* c, uint32_t a0, uint32_t a1,
                                         uint32_t a2, uint32_t a3,
                                         uint32_t b0, uint32_t b1) {
    asm volatile("mma.sync.aligned.m16n8k16.row.col.f32.bf16.bf16.f32 "
                 "{%0,%1,%2,%3}, {%4,%5,%6,%7}, {%8,%9}, {%0,%1,%2,%3};"
                 : "+f"(c[0]), "+f"(c[1]), "+f"(c[2]), "+f"(c[3])
                 : "r"(a0), "r"(a1), "r"(a2), "r"(a3), "r"(b0), "r"(b1));
}

// ---- slot maps (compile-time) ----
// Slot S (0..77), lane rotation c applied via data (y[i] = xpair[(i+4c)&15]):
//   S<72:  d=S>>3 (0=diag), a=(S>>1)&3, h=S&1 ->
//          u = half h of y[a] (broadcast), v = y[a+d] natural pair
//   72..75: linear pair y[S-72];  76: {bias=1,0};  77: zero pad
__host__ __device__ constexpr int sD(int S)  { return S >> 3; }
__host__ __device__ constexpr int sA(int S)  { return (S >> 1) & 3; }
__host__ __device__ constexpr int sH(int S)  { return S & 1; }
__host__ __device__ constexpr int sI1(int S) { return sD(S) == 0 ? sA(S) : sA(S) + sD(S); }

template <int S>
__device__ __forceinline__ uint32_t pairA(const uint32_t* y) {
    if (S >= 77) return 0u;                 // zero pad
    if (S == 76) return 0x00003F80u;        // {bias=1, 0}
    if (S >= 72) return y[S - 72];          // linear: natural pair
    const uint32_t s0 = y[sA(S)];
    const uint32_t u = __byte_perm(s0, s0, sH(S) ? 0x3232 : 0x1010);  // bcast half
    uint32_t r;
    asm("mul.rn.bf16x2 %0, %1, %2;" : "=r"(r) : "r"(u), "r"(y[sI1(S)]));
    return r;
}

// ---- runtime W for B-table init (mirrors the slot map; dups get 0) ----
__device__ float wsym(const float* __restrict__ W, int i, int m, int n) {
    if (i == m) return __ldg(&W[(33 + i * 32 + i) * 32 + n]);
    return __ldg(&W[(33 + i * 32 + m) * 32 + n]) + __ldg(&W[(33 + m * 32 + i) * 32 + n]);
}

__device__ float wcell(const float* __restrict__ W, int S, int c, int j, int n) {
    if (S >= 77) return 0.0f;
    if (S == 76) return (j == 0 && c == 0) ? __ldg(&W[n]) : 0.0f;
    if (S >= 72) {
        const int pv = ((S - 72) + 4 * c) & 15;
        return __ldg(&W[(1 + 2 * pv + j) * 32 + n]);
    }
    const int d = S >> 3, a = (S >> 1) & 3, h = S & 1;
    const int A = (a + 4 * c) & 15;
    if (d == 0) {
        if (h == 1 && j == 0) return 0.0f;           // dup {2A+1, 2A}
        return wsym(W, 2 * A + h, 2 * A + j, n);
    }
    if (d == 8 && A >= 8) return 0.0f;               // reversed copy of {A-8, A}
    const int B = (A + d) & 15;
    return wsym(W, 2 * A + h, 2 * B + j, n);
}

} // namespace

// B-fragment tables: [0, NKT*32) = Lo (n 0..15), [NKT*32, 2*NKT*32) = Hi.
__device__ uint4 g_Bf[2 * NKT * 32];

__global__ void bf_init_kernel(const float* __restrict__ W) {
    const int idx = blockIdx.x * blockDim.x + threadIdx.x;
    if (idx >= 2 * NKT * 32) return;
    const int t   = idx / (NKT * 32);
    const int rem = idx - t * (NKT * 32);
    const int kt  = rem >> 5;
    const int l   = rem & 31;
    const int c   = l & 3;
    const int n0  = (l >> 2) + t * 16;
    uint4 q;
    q.x = pack2(wcell(W, 2 * kt,     c, 0, n0),     wcell(W, 2 * kt,     c, 1, n0));
    q.y = pack2(wcell(W, 2 * kt + 1, c, 0, n0),     wcell(W, 2 * kt + 1, c, 1, n0));
    q.z = pack2(wcell(W, 2 * kt,     c, 0, n0 + 8), wcell(W, 2 * kt,     c, 1, n0 + 8));
    q.w = pack2(wcell(W, 2 * kt + 1, c, 0, n0 + 8), wcell(W, 2 * kt + 1, c, 1, n0 + 8));
    g_Bf[idx] = q;
}

__global__ void __launch_bounds__(256, 3)
tmpnn_kernel(const float* __restrict__ X, float* __restrict__ out)
{
    extern __shared__ char smem[];
    uint32_t* xsb = reinterpret_cast<uint32_t*>(smem + OFF_XB); // [128][20] bf16x2

    const int tid  = threadIdx.x;
    const int lane = tid & 31;
    const int w    = tid >> 5;
    const int c    = lane & 3;               // fragment column group / data rotation
    const int r0   = w * 16 + (lane >> 2);   // this lane's mma rows: r0, r0+8
    const int cb   = c * 2;                  // accumulator col base

    // ---- stage bf16x2 X copy ----
    const float* Xb = X + (size_t)blockIdx.x * 4096;
    for (int i = tid; i < 128 * 16; i += 256) {
        const int rr = i >> 4, j = i & 15;
        const float2 v = __ldg(reinterpret_cast<const float2*>(Xb + rr * 32 + 2 * j));
        xsb[rr * XBSTR + j] = pack2(v.x, v.y);
    }

    // ---- fp32 residual in mma-accumulator layout ----
    float res[4][4];
    #pragma unroll
    for (int nt = 0; nt < 4; ++nt) {
        const int cc = nt * 8 + cb;
        const float2 v0 = __ldg(reinterpret_cast<const float2*>(Xb + r0 * 32 + cc));
        const float2 v1 = __ldg(reinterpret_cast<const float2*>(Xb + (r0 + 8) * 32 + cc));
        res[nt][0] = v0.x; res[nt][1] = v0.y;
        res[nt][2] = v1.x; res[nt][3] = v1.y;
    }
    __syncthreads();   // xsb visible (only CTA-wide barrier)

    const uint4* BfL = g_Bf + lane;
    const uint4* BfH = g_Bf + (NKT * 32) + lane;

    for (int step = 0; step < N_STEPS; ++step) {
        const bool full = (step != N_STEPS - 1);   // last step: only n 0..7 needed

        // rotated pair regs: y[i] = xpair[(i + 4c) & 15]; only y[0..11] used.
        uint32_t y0[12], y1[12];
        #pragma unroll
        for (int q = 0; q < 3; ++q) {
            const int ch = ((q + c) & 3) * 4;
            const uint4 t0 = *reinterpret_cast<const uint4*>(&xsb[r0 * XBSTR + ch]);
            const uint4 t1 = *reinterpret_cast<const uint4*>(&xsb[(r0 + 8) * XBSTR + ch]);
            y0[4*q] = t0.x; y0[4*q+1] = t0.y; y0[4*q+2] = t0.z; y0[4*q+3] = t0.w;
            y1[4*q] = t1.x; y1[4*q+1] = t1.y; y1[4*q+2] = t1.z; y1[4*q+3] = t1.w;
        }

#define TILE(T) {                                                        \
            const uint32_t a0 = pairA<2*(T)>(y0);                        \
            const uint32_t a1 = pairA<2*(T)>(y1);                        \
            const uint32_t a2 = pairA<2*(T)+1>(y0);                      \
            const uint32_t a3 = pairA<2*(T)+1>(y1);                      \
            const uint4 ql = __ldg(BfL + (T) * 32);                      \
            mma16816(res[0], a0, a1, a2, a3, ql.x, ql.y);                \
            if (full) {                                                  \
                mma16816(res[1], a0, a1, a2, a3, ql.z, ql.w);            \
                const uint4 qh = __ldg(BfH + (T) * 32);                  \
                mma16816(res[2], a0, a1, a2, a3, qh.x, qh.y);            \
                mma16816(res[3], a0, a1, a2, a3, qh.z, qh.w);            \
            }                                                            \
        }
        TILE(0)  TILE(1)  TILE(2)  TILE(3)  TILE(4)  TILE(5)  TILE(6)
        TILE(7)  TILE(8)  TILE(9)  TILE(10) TILE(11) TILE(12) TILE(13)
        TILE(14) TILE(15) TILE(16) TILE(17) TILE(18) TILE(19) TILE(20)
        TILE(21) TILE(22) TILE(23) TILE(24) TILE(25) TILE(26) TILE(27)
        TILE(28) TILE(29) TILE(30) TILE(31) TILE(32) TILE(33) TILE(34)
        TILE(35) TILE(36) TILE(37) TILE(38)
#undef TILE

        // ---- epilogue: refresh bf16x2 copy from accumulator registers ----
        if (full) {
            __syncwarp();   // y reads of this step done before xsb overwrite
            #pragma unroll
            for (int nt = 0; nt < 4; ++nt) {
                const int cc = nt * 8 + cb;
                xsb[r0 * XBSTR + (cc >> 1)]       = pack2(res[nt][0], res[nt][1]);
                xsb[(r0 + 8) * XBSTR + (cc >> 1)] = pack2(res[nt][2], res[nt][3]);
            }
            __syncwarp();   // visible to next step's y reload
        }
    }

    if (c == 0) {
        out[(size_t)blockIdx.x * 128 + r0]     = res[0][0];
        out[(size_t)blockIdx.x * 128 + r0 + 8] = res[0][2];
    }
}

extern "C" void kernel_launch(void* const* d_in, const int* in_sizes, int n_in,
                              void* d_out, int out_size) {
    const float* X = (const float*)d_in[0];
    const float* W = (const float*)d_in[1];
    float* out = (float*)d_out;
    const int rows = in_sizes[0] / 32;
    const int blocks = rows / 128;
    bf_init_kernel<<<(2 * NKT * 32 + 255) / 256, 256>>>(W);
    cudaFuncSetAttribute(tmpnn_kernel, cudaFuncAttributeMaxDynamicSharedMemorySize,
                         SMEM_BYTES);
    tmpnn_kernel<<<blocks, 256, SMEM_BYTES>>>(X, out);
}